// round 3
// baseline (speedup 1.0000x reference)
#include <cuda_runtime.h>
#include <cstdint>

// ============================================================================
// out[4096,1000] = core[4096,4096] @ weights[1000,4096]^T   (fp32)
//
// mma.sync tf32 path (tcgen05 is compile-gated off at sm_103 base target).
// R3 change vs R2: 512 threads / 16 warps (occ 12.5%->25%) with 64x32 warp
// tiles to hide LDS+MMA latency; refill cp.async issued right after the
// barrier so loads overlap the whole compute phase.
// ============================================================================

#define MDIM 4096
#define NDIM 1000
#define KDIM 4096

#define BM 256
#define BN 128
#define BK 16
#define BKP 20                      // padded row (floats): conflict-free scalar LDS
#define STAGES 4
#define KTILES (KDIM / BK)          // 256
#define THREADS 512

#define A_STG (BM * BKP)            // 5120 floats
#define B_STG (BN * BKP)            // 2560 floats
#define STG (A_STG + B_STG)         // 7680 floats
#define SMEM_BYTES (STAGES * STG * 4)   // 122880 B

// ---------------------------------------------------------------------------
__device__ __forceinline__ uint32_t smem_u32(const void* p) {
    uint32_t a;
    asm("{ .reg .u64 t; cvta.to.shared.u64 t, %1; cvt.u32.u64 %0, t; }" : "=r"(a) : "l"(p));
    return a;
}

__device__ __forceinline__ void cp16(uint32_t dst, const float* src, uint32_t src_bytes) {
    asm volatile("cp.async.cg.shared.global [%0], [%1], 16, %2;"
                 :: "r"(dst), "l"(src), "r"(src_bytes) : "memory");
}
#define CP_COMMIT() asm volatile("cp.async.commit_group;" ::: "memory")
#define CP_WAIT2()  asm volatile("cp.async.wait_group 2;"  ::: "memory")

__device__ __forceinline__ uint32_t f2tf(float f) {
    uint32_t r;
    asm("cvt.rna.tf32.f32 %0, %1;" : "=r"(r) : "f"(f));
    return r;
}

__device__ __forceinline__ void mma_tf32(float c[4],
                                         const uint32_t a[4], const uint32_t b[2]) {
    asm volatile(
        "mma.sync.aligned.m16n8k8.row.col.f32.tf32.tf32.f32 "
        "{%0,%1,%2,%3}, {%4,%5,%6,%7}, {%8,%9}, {%0,%1,%2,%3};"
        : "+f"(c[0]), "+f"(c[1]), "+f"(c[2]), "+f"(c[3])
        : "r"(a[0]), "r"(a[1]), "r"(a[2]), "r"(a[3]), "r"(b[0]), "r"(b[1]));
}

// ---------------------------------------------------------------------------
__global__ void __launch_bounds__(THREADS, 1)
tol_gemm_tf32(const float* __restrict__ A,     // [4096, 4096]
              const float* __restrict__ Bw,    // [1000, 4096]
              float* __restrict__ C) {         // [4096, 1000]
    extern __shared__ float smem[];
    const int tid  = threadIdx.x;
    const int wid  = tid >> 5;
    const int lane = tid & 31;

    const int m0 = blockIdx.y * BM;
    const int n0 = blockIdx.x * BN;

    const int warp_m = wid & 3;      // 0..3  (64-row band)
    const int warp_n = wid >> 2;     // 0..3  (32-col band)

    // global->smem load mapping: 512 threads, each copies 16B chunks
    const int lrow = tid >> 2;       // 0..127
    const int lc4  = tid & 3;        // which 16B of the 64B (BK=16 floats) row
    const uint32_t sb = smem_u32(smem);

    const float* ag0 = A + (size_t)(m0 + lrow) * KDIM + lc4 * 4;
    const float* ag1 = ag0 + (size_t)128 * KDIM;

    int brow = n0 + lrow;
    const uint32_t bok = (brow < NDIM) ? 16u : 0u;
    if (brow >= NDIM) brow = NDIM - 1;            // keep address in-range; 0-fill
    const float* bg = Bw + (size_t)brow * KDIM + lc4 * 4;

    const uint32_t a_dst0 = sb + (uint32_t)(lrow * BKP + lc4 * 4) * 4;
    const uint32_t a_dst1 = a_dst0 + (uint32_t)(128 * BKP * 4);
    const uint32_t b_dst0 = sb + (uint32_t)(A_STG + lrow * BKP + lc4 * 4) * 4;

#define ISSUE_STAGE(kt, s) do {                                                 \
        const uint32_t soff = (uint32_t)(s) * (STG * 4);                        \
        const size_t  koff  = (size_t)(kt) * BK;                                \
        cp16(a_dst0 + soff, ag0 + koff, 16);                                    \
        cp16(a_dst1 + soff, ag1 + koff, 16);                                    \
        cp16(b_dst0 + soff, bg  + koff, bok);                                   \
    } while (0)

    float acc[4][4][4];
    #pragma unroll
    for (int t = 0; t < 4; t++)
        #pragma unroll
        for (int u = 0; u < 4; u++)
            #pragma unroll
            for (int i = 0; i < 4; i++)
                acc[t][u][i] = 0.0f;

    // prologue: fill STAGES-1 stages
    #pragma unroll
    for (int p = 0; p < STAGES - 1; p++) {
        ISSUE_STAGE(p, p);
        CP_COMMIT();
    }

    const int ar0 = warp_m * 64 + (lane >> 2);   // A row in tile (+t*16, +8)
    const int ac0 = lane & 3;                    // A col in k-chunk (+ks*8, +4)
    const int bn0 = warp_n * 32 + (lane >> 2);   // B row (n) in tile (+u*8)

    for (int kt = 0; kt < KTILES; kt++) {
        const int s = kt & (STAGES - 1);
        CP_WAIT2();
        __syncthreads();

        // refill FIRST so the loads overlap the whole compute phase below.
        // stage (s+3)&3 was consumed at iteration kt-1; barrier above makes
        // overwriting it safe now.
        const int kn = kt + STAGES - 1;
        if (kn < KTILES) {
            ISSUE_STAGE(kn, kn & (STAGES - 1));
        }
        CP_COMMIT();

        const float* as = smem + s * STG;
        const float* bs = as + A_STG;

        #pragma unroll
        for (int ks = 0; ks < 2; ks++) {
            uint32_t af[4][4];
            #pragma unroll
            for (int t = 0; t < 4; t++) {
                const float* p = as + (ar0 + t * 16) * BKP + ks * 8 + ac0;
                af[t][0] = f2tf(p[0]);
                af[t][1] = f2tf(p[8 * BKP]);
                af[t][2] = f2tf(p[4]);
                af[t][3] = f2tf(p[8 * BKP + 4]);
            }
            uint32_t bf[4][2];
            #pragma unroll
            for (int u = 0; u < 4; u++) {
                const float* p = bs + (bn0 + u * 8) * BKP + ks * 8 + ac0;
                bf[u][0] = f2tf(p[0]);
                bf[u][1] = f2tf(p[4]);
            }
            #pragma unroll
            for (int t = 0; t < 4; t++)
                #pragma unroll
                for (int u = 0; u < 4; u++)
                    mma_tf32(acc[t][u], af[t], bf[u]);
        }
    }

    // ---- epilogue: each warp writes its 64x32 region, guard N edge ----
    #pragma unroll
    for (int t = 0; t < 4; t++) {
        const int gr = m0 + warp_m * 64 + t * 16 + (lane >> 2);
        #pragma unroll
        for (int u = 0; u < 4; u++) {
            const int gc = n0 + warp_n * 32 + u * 8 + (lane & 3) * 2;
            if (gc < NDIM) {   // NDIM even; float2 never straddles the edge
                float2 v0 = make_float2(acc[t][u][0], acc[t][u][1]);
                float2 v1 = make_float2(acc[t][u][2], acc[t][u][3]);
                *reinterpret_cast<float2*>(C + (size_t)gr * NDIM + gc) = v0;
                *reinterpret_cast<float2*>(C + (size_t)(gr + 8) * NDIM + gc) = v1;
            }
        }
    }
}

// ---------------------------------------------------------------------------
extern "C" void kernel_launch(void* const* d_in, const int* in_sizes, int n_in,
                              void* d_out, int out_size) {
    const float* core = (const float*)d_in[0];   // [4096, 16,16,16] = [4096,4096]
    const float* wts  = (const float*)d_in[1];   // [1000, 4096]
    float* out = (float*)d_out;                  // [4096, 1000]

    cudaFuncSetAttribute(tol_gemm_tf32,
                         cudaFuncAttributeMaxDynamicSharedMemorySize, SMEM_BYTES);

    dim3 grid((NDIM + BN - 1) / BN, MDIM / BM, 1);   // (8, 16) = 128 CTAs
    tol_gemm_tf32<<<grid, THREADS, SMEM_BYTES>>>(core, wts, out);
}

// round 4
// speedup vs baseline: 1.0013x; 1.0013x over previous
#include <cuda_runtime.h>
#include <cstdint>

// ============================================================================
// out[4096,1000] = core[4096,4096] @ weights[1000,4096]^T   (fp32)
//
// mma.sync tf32 path. R4 vs R2: same per-SM work shape (8 warps of 64x64
// tiles), but split into TWO independent 128-thread CTAs per SM
// (BM=128,BN=128, grid 8x32=256, 2 CTAs/SM). When one CTA stalls at its
// barrier / cp.async.wait, the other keeps the HMMA pipe busy.
// ============================================================================

#define MDIM 4096
#define NDIM 1000
#define KDIM 4096

#define BM 128
#define BN 128
#define BK 16
#define BKP 20                      // padded row (floats): conflict-free scalar LDS
#define STAGES 4
#define KTILES (KDIM / BK)          // 256
#define THREADS 128

#define A_STG (BM * BKP)            // 2560 floats
#define B_STG (BN * BKP)            // 2560 floats
#define STG (A_STG + B_STG)         // 5120 floats
#define SMEM_BYTES (STAGES * STG * 4)   // 81920 B per CTA -> 2 CTAs/SM

// ---------------------------------------------------------------------------
__device__ __forceinline__ uint32_t smem_u32(const void* p) {
    uint32_t a;
    asm("{ .reg .u64 t; cvta.to.shared.u64 t, %1; cvt.u32.u64 %0, t; }" : "=r"(a) : "l"(p));
    return a;
}

__device__ __forceinline__ void cp16(uint32_t dst, const float* src, uint32_t src_bytes) {
    asm volatile("cp.async.cg.shared.global [%0], [%1], 16, %2;"
                 :: "r"(dst), "l"(src), "r"(src_bytes) : "memory");
}
#define CP_COMMIT() asm volatile("cp.async.commit_group;" ::: "memory")
#define CP_WAIT2()  asm volatile("cp.async.wait_group 2;"  ::: "memory")

__device__ __forceinline__ uint32_t f2tf(float f) {
    uint32_t r;
    asm("cvt.rna.tf32.f32 %0, %1;" : "=r"(r) : "f"(f));
    return r;
}

__device__ __forceinline__ void mma_tf32(float c[4],
                                         const uint32_t a[4], const uint32_t b[2]) {
    asm volatile(
        "mma.sync.aligned.m16n8k8.row.col.f32.tf32.tf32.f32 "
        "{%0,%1,%2,%3}, {%4,%5,%6,%7}, {%8,%9}, {%0,%1,%2,%3};"
        : "+f"(c[0]), "+f"(c[1]), "+f"(c[2]), "+f"(c[3])
        : "r"(a[0]), "r"(a[1]), "r"(a[2]), "r"(a[3]), "r"(b[0]), "r"(b[1]));
}

// ---------------------------------------------------------------------------
__global__ void __launch_bounds__(THREADS, 2)
tol_gemm_tf32(const float* __restrict__ A,     // [4096, 4096]
              const float* __restrict__ Bw,    // [1000, 4096]
              float* __restrict__ C) {         // [4096, 1000]
    extern __shared__ float smem[];
    const int tid  = threadIdx.x;
    const int wid  = tid >> 5;
    const int lane = tid & 31;

    const int m0 = blockIdx.y * BM;
    const int n0 = blockIdx.x * BN;

    const int warp_m = wid & 1;      // 0..1  (64-row band)
    const int warp_n = wid >> 1;     // 0..1  (64-col band)

    // global->smem load mapping: 128 threads, each copies 4x16B for A, 4x16B for B
    const int lrow = tid >> 2;       // 0..31
    const int lc4  = tid & 3;        // which 16B of the 64B (BK=16 floats) row
    const uint32_t sb = smem_u32(smem);

    const float* ag[4];
    #pragma unroll
    for (int i = 0; i < 4; i++)
        ag[i] = A + (size_t)(m0 + lrow + i * 32) * KDIM + lc4 * 4;

    const float* bg[4];
    uint32_t bok[4];
    #pragma unroll
    for (int i = 0; i < 4; i++) {
        int brow = n0 + lrow + i * 32;
        bok[i] = (brow < NDIM) ? 16u : 0u;
        if (brow >= NDIM) brow = NDIM - 1;       // keep address in-range; 0-fill
        bg[i] = Bw + (size_t)brow * KDIM + lc4 * 4;
    }

    const uint32_t a_dst0 = sb + (uint32_t)(lrow * BKP + lc4 * 4) * 4;
    const uint32_t b_dst0 = sb + (uint32_t)(A_STG + lrow * BKP + lc4 * 4) * 4;

#define ISSUE_STAGE(kt, s) do {                                                 \
        const uint32_t soff = (uint32_t)(s) * (STG * 4);                        \
        const size_t  koff  = (size_t)(kt) * BK;                                \
        _Pragma("unroll")                                                       \
        for (int i = 0; i < 4; i++)                                             \
            cp16(a_dst0 + soff + (uint32_t)(i * 32 * BKP * 4), ag[i] + koff, 16);\
        _Pragma("unroll")                                                       \
        for (int i = 0; i < 4; i++)                                             \
            cp16(b_dst0 + soff + (uint32_t)(i * 32 * BKP * 4), bg[i] + koff, bok[i]);\
    } while (0)

    float acc[4][8][4];
    #pragma unroll
    for (int t = 0; t < 4; t++)
        #pragma unroll
        for (int u = 0; u < 8; u++)
            #pragma unroll
            for (int i = 0; i < 4; i++)
                acc[t][u][i] = 0.0f;

    // prologue: fill STAGES-1 stages
    #pragma unroll
    for (int p = 0; p < STAGES - 1; p++) {
        ISSUE_STAGE(p, p);
        CP_COMMIT();
    }

    const int ar0 = warp_m * 64 + (lane >> 2);   // A row in tile (+t*16, +8)
    const int ac0 = lane & 3;                    // A col in k-chunk (+ks*8, +4)
    const int bn0 = warp_n * 64 + (lane >> 2);   // B row (n) in tile (+u*8)

    for (int kt = 0; kt < KTILES; kt++) {
        const int s = kt & (STAGES - 1);
        CP_WAIT2();
        __syncthreads();

        // refill first so loads overlap the compute phase below
        const int kn = kt + STAGES - 1;
        if (kn < KTILES) {
            ISSUE_STAGE(kn, kn & (STAGES - 1));
        }
        CP_COMMIT();

        const float* as = smem + s * STG;
        const float* bs = as + A_STG;

        #pragma unroll
        for (int ks = 0; ks < 2; ks++) {
            uint32_t af[4][4];
            #pragma unroll
            for (int t = 0; t < 4; t++) {
                const float* p = as + (ar0 + t * 16) * BKP + ks * 8 + ac0;
                af[t][0] = f2tf(p[0]);
                af[t][1] = f2tf(p[8 * BKP]);
                af[t][2] = f2tf(p[4]);
                af[t][3] = f2tf(p[8 * BKP + 4]);
            }
            uint32_t bf[8][2];
            #pragma unroll
            for (int u = 0; u < 8; u++) {
                const float* p = bs + (bn0 + u * 8) * BKP + ks * 8 + ac0;
                bf[u][0] = f2tf(p[0]);
                bf[u][1] = f2tf(p[4]);
            }
            #pragma unroll
            for (int t = 0; t < 4; t++)
                #pragma unroll
                for (int u = 0; u < 8; u++)
                    mma_tf32(acc[t][u], af[t], bf[u]);
        }
    }

    // ---- epilogue: each warp writes its 64x64 region, guard N edge ----
    #pragma unroll
    for (int t = 0; t < 4; t++) {
        const int gr = m0 + warp_m * 64 + t * 16 + (lane >> 2);
        #pragma unroll
        for (int u = 0; u < 8; u++) {
            const int gc = n0 + warp_n * 64 + u * 8 + (lane & 3) * 2;
            if (gc < NDIM) {   // NDIM even; float2 never straddles the edge
                float2 v0 = make_float2(acc[t][u][0], acc[t][u][1]);
                float2 v1 = make_float2(acc[t][u][2], acc[t][u][3]);
                *reinterpret_cast<float2*>(C + (size_t)gr * NDIM + gc) = v0;
                *reinterpret_cast<float2*>(C + (size_t)(gr + 8) * NDIM + gc) = v1;
            }
        }
    }
}

// ---------------------------------------------------------------------------
extern "C" void kernel_launch(void* const* d_in, const int* in_sizes, int n_in,
                              void* d_out, int out_size) {
    const float* core = (const float*)d_in[0];   // [4096, 16,16,16] = [4096,4096]
    const float* wts  = (const float*)d_in[1];   // [1000, 4096]
    float* out = (float*)d_out;                  // [4096, 1000]

    cudaFuncSetAttribute(tol_gemm_tf32,
                         cudaFuncAttributeMaxDynamicSharedMemorySize, SMEM_BYTES);

    dim3 grid((NDIM + BN - 1) / BN, MDIM / BM, 1);   // (8, 32) = 256 CTAs, 2/SM
    tol_gemm_tf32<<<grid, THREADS, SMEM_BYTES>>>(core, wts, out);
}

// round 5
// speedup vs baseline: 1.2167x; 1.2151x over previous
#include <cuda_runtime.h>
#include <cstdint>

// ============================================================================
// out[4096,1000] = core[4096,4096] @ weights[1000,4096]^T   (fp32)
//
// mma.sync tf32. R5 vs R2 (best=260us): same CTA geometry (BM256xBN128,
// 256 thr, 8 warps x 64x64, 128 CTAs = 1 clean wave), but BK 16->32
// (half the barrier phases), 3-stage cp.async, and explicit register
// double-buffering of MMA fragments across the 4 ks-subchunks so LDS
// latency hides behind the HMMA stream.
// ============================================================================

#define MDIM 4096
#define NDIM 1000
#define KDIM 4096

#define BM 256
#define BN 128
#define BK 32
#define BKP 36                      // padded row (floats): conflict-free scalar LDS
#define STAGES 3
#define KTILES (KDIM / BK)          // 128
#define THREADS 256

#define A_STG (BM * BKP)            // 9216 floats
#define B_STG (BN * BKP)            // 4608 floats
#define STG (A_STG + B_STG)         // 13824 floats
#define SMEM_BYTES (STAGES * STG * 4)   // 165888 B

// ---------------------------------------------------------------------------
__device__ __forceinline__ uint32_t smem_u32(const void* p) {
    uint32_t a;
    asm("{ .reg .u64 t; cvta.to.shared.u64 t, %1; cvt.u32.u64 %0, t; }" : "=r"(a) : "l"(p));
    return a;
}

__device__ __forceinline__ void cp16(uint32_t dst, const float* src, uint32_t src_bytes) {
    asm volatile("cp.async.cg.shared.global [%0], [%1], 16, %2;"
                 :: "r"(dst), "l"(src), "r"(src_bytes) : "memory");
}
#define CP_COMMIT() asm volatile("cp.async.commit_group;" ::: "memory")
#define CP_WAIT1()  asm volatile("cp.async.wait_group 1;"  ::: "memory")

__device__ __forceinline__ uint32_t f2tf(float f) {
    uint32_t r;
    asm("cvt.rna.tf32.f32 %0, %1;" : "=r"(r) : "f"(f));
    return r;
}

__device__ __forceinline__ void mma_tf32(float c[4],
                                         const uint32_t a[4], const uint32_t b[2]) {
    asm volatile(
        "mma.sync.aligned.m16n8k8.row.col.f32.tf32.tf32.f32 "
        "{%0,%1,%2,%3}, {%4,%5,%6,%7}, {%8,%9}, {%0,%1,%2,%3};"
        : "+f"(c[0]), "+f"(c[1]), "+f"(c[2]), "+f"(c[3])
        : "r"(a[0]), "r"(a[1]), "r"(a[2]), "r"(a[3]), "r"(b[0]), "r"(b[1]));
}

// ---------------------------------------------------------------------------
__global__ void __launch_bounds__(THREADS, 1)
tol_gemm_tf32(const float* __restrict__ A,     // [4096, 4096]
              const float* __restrict__ Bw,    // [1000, 4096]
              float* __restrict__ C) {         // [4096, 1000]
    extern __shared__ float smem[];
    const int tid  = threadIdx.x;
    const int wid  = tid >> 5;
    const int lane = tid & 31;

    const int m0 = blockIdx.y * BM;
    const int n0 = blockIdx.x * BN;

    const int warp_m = wid >> 1;     // 0..3  (64-row band)
    const int warp_n = wid & 1;      // 0..1  (64-col band)

    // global->smem: 256 threads; each row is 128B = 8 x 16B chunks
    const int lrow = tid >> 3;       // 0..31
    const int lc8  = tid & 7;        // which 16B chunk of the 128B row
    const uint32_t sb = smem_u32(smem);

    const float* agbase = A + (size_t)(m0 + lrow) * KDIM + lc8 * 4;

    const float* bg[4];
    uint32_t bok[4];
    #pragma unroll
    for (int i = 0; i < 4; i++) {
        int brow = n0 + lrow + i * 32;
        bok[i] = (brow < NDIM) ? 16u : 0u;
        if (brow >= NDIM) brow = NDIM - 1;       // keep address in-range; 0-fill
        bg[i] = Bw + (size_t)brow * KDIM + lc8 * 4;
    }

    const uint32_t a_dst0 = sb + (uint32_t)(lrow * BKP + lc8 * 4) * 4;
    const uint32_t b_dst0 = sb + (uint32_t)(A_STG + lrow * BKP + lc8 * 4) * 4;

#define ISSUE_STAGE(kt, s) do {                                                  \
        const uint32_t soff = (uint32_t)(s) * (STG * 4);                         \
        const size_t  koff  = (size_t)(kt) * BK;                                 \
        _Pragma("unroll")                                                        \
        for (int i = 0; i < 8; i++)                                              \
            cp16(a_dst0 + soff + (uint32_t)(i * 32 * BKP * 4),                   \
                 agbase + koff + (size_t)i * 32 * KDIM, 16);                     \
        _Pragma("unroll")                                                        \
        for (int i = 0; i < 4; i++)                                              \
            cp16(b_dst0 + soff + (uint32_t)(i * 32 * BKP * 4),                   \
                 bg[i] + koff, bok[i]);                                          \
    } while (0)

    float acc[4][8][4];
    #pragma unroll
    for (int t = 0; t < 4; t++)
        #pragma unroll
        for (int u = 0; u < 8; u++)
            #pragma unroll
            for (int i = 0; i < 4; i++)
                acc[t][u][i] = 0.0f;

    // prologue: fill STAGES-1 = 2 stages
    #pragma unroll
    for (int p = 0; p < STAGES - 1; p++) {
        ISSUE_STAGE(p, p);
        CP_COMMIT();
    }

    const int ar0 = warp_m * 64 + (lane >> 2);   // A row in tile (+t*16, +8)
    const int ac0 = lane & 3;                    // A col in k-subchunk (+ks*8, +4)
    const int bn0 = warp_n * 64 + (lane >> 2);   // B row (n) in tile (+u*8)

    // fragment double buffers
    uint32_t af[2][4][4];
    uint32_t bf[2][8][2];

#define LOAD_FRAG(buf, as, bs, ksv) do {                                         \
        _Pragma("unroll")                                                        \
        for (int t = 0; t < 4; t++) {                                            \
            const float* p = (as) + (ar0 + t * 16) * BKP + (ksv) * 8 + ac0;      \
            af[buf][t][0] = f2tf(p[0]);                                          \
            af[buf][t][1] = f2tf(p[8 * BKP]);                                    \
            af[buf][t][2] = f2tf(p[4]);                                          \
            af[buf][t][3] = f2tf(p[8 * BKP + 4]);                                \
        }                                                                        \
        _Pragma("unroll")                                                        \
        for (int u = 0; u < 8; u++) {                                            \
            const float* p = (bs) + (bn0 + u * 8) * BKP + (ksv) * 8 + ac0;       \
            bf[buf][u][0] = f2tf(p[0]);                                          \
            bf[buf][u][1] = f2tf(p[4]);                                          \
        }                                                                        \
    } while (0)

    int s = 0;
    for (int kt = 0; kt < KTILES; kt++) {
        CP_WAIT1();
        __syncthreads();

        const float* as = smem + s * STG;
        const float* bs = as + A_STG;

        // first fragment of this phase
        LOAD_FRAG(0, as, bs, 0);

        // refill the stage consumed two phases ago (safe after the barrier)
        const int kn = kt + STAGES - 1;
        if (kn < KTILES) {
            int sr = s + STAGES - 1; if (sr >= STAGES) sr -= STAGES;
            ISSUE_STAGE(kn, sr);
        }
        CP_COMMIT();

        // pipelined ks loop: load frag(ks+1) before mma(ks)
        #pragma unroll
        for (int ks = 0; ks < 4; ks++) {
            const int cur = ks & 1;
            if (ks < 3) LOAD_FRAG(cur ^ 1, as, bs, ks + 1);
            #pragma unroll
            for (int t = 0; t < 4; t++)
                #pragma unroll
                for (int u = 0; u < 8; u++)
                    mma_tf32(acc[t][u], af[cur][t], bf[cur][u]);
        }

        if (++s == STAGES) s = 0;
    }

    // ---- epilogue: each warp writes its 64x64 region, guard N edge ----
    #pragma unroll
    for (int t = 0; t < 4; t++) {
        const int gr = m0 + warp_m * 64 + t * 16 + (lane >> 2);
        #pragma unroll
        for (int u = 0; u < 8; u++) {
            const int gc = n0 + warp_n * 64 + u * 8 + (lane & 3) * 2;
            if (gc < NDIM) {   // NDIM even; float2 never straddles the edge
                float2 v0 = make_float2(acc[t][u][0], acc[t][u][1]);
                float2 v1 = make_float2(acc[t][u][2], acc[t][u][3]);
                *reinterpret_cast<float2*>(C + (size_t)gr * NDIM + gc) = v0;
                *reinterpret_cast<float2*>(C + (size_t)(gr + 8) * NDIM + gc) = v1;
            }
        }
    }
}

// ---------------------------------------------------------------------------
extern "C" void kernel_launch(void* const* d_in, const int* in_sizes, int n_in,
                              void* d_out, int out_size) {
    const float* core = (const float*)d_in[0];   // [4096, 16,16,16] = [4096,4096]
    const float* wts  = (const float*)d_in[1];   // [1000, 4096]
    float* out = (float*)d_out;                  // [4096, 1000]

    cudaFuncSetAttribute(tol_gemm_tf32,
                         cudaFuncAttributeMaxDynamicSharedMemorySize, SMEM_BYTES);

    dim3 grid((NDIM + BN - 1) / BN, MDIM / BM, 1);   // (8, 16) = 128 CTAs, 1 wave
    tol_gemm_tf32<<<grid, THREADS, SMEM_BYTES>>>(core, wts, out);
}

// round 6
// speedup vs baseline: 1.3649x; 1.1218x over previous
#include <cuda_runtime.h>
#include <cstdint>

// ============================================================================
// out[4096,1000] = core[4096,4096] @ weights[1000,4096]^T   (fp32)
//
// R6: two-phase approach.
//  (1) pack kernels: rewrite A,B into fragment-major tf32-rounded scratch
//      (__device__ globals) so each thread's mma fragment is one contiguous
//      LDS.128 / LDS.64, and all cvt.rna work leaves the GEMM mainloop.
//  (2) GEMM: BM256xBN128, 8 warps x 64x64, BK=32, 4-stage cp.async of
//      contiguous packed tiles, ks-double-buffered fragments, zero cvt,
//      12 LDS + 32 HMMA per ks per warp.
// ============================================================================

#define MDIM 4096
#define NDIM 1000
#define KDIM 4096

#define BM 256
#define BN 128
#define BK 32
#define KTILES (KDIM / BK)            // 128
#define STAGES 4
#define THREADS 256

#define A_TILE_BYTES (BM * BK * 4)    // 32768
#define B_TILE_BYTES (BN * BK * 4)    // 16384
#define STAGE_BYTES  (A_TILE_BYTES + B_TILE_BYTES)   // 49152
#define SMEM_BYTES   (STAGES * STAGE_BYTES)          // 196608

// packed scratch: A' = [16 mtiles][128 kt][2048 x 16B], B' = [8 ntiles][128 kt][2048 x 8B]
__device__ uint4 g_Ap[16 * 128 * 2048];   // 64 MB
__device__ uint2 g_Bp[8 * 128 * 2048];    // 16 MB

// ---------------------------------------------------------------------------
__device__ __forceinline__ uint32_t smem_u32(const void* p) {
    uint32_t a;
    asm("{ .reg .u64 t; cvta.to.shared.u64 t, %1; cvt.u32.u64 %0, t; }" : "=r"(a) : "l"(p));
    return a;
}

__device__ __forceinline__ void cp16(uint32_t dst, const void* src) {
    asm volatile("cp.async.cg.shared.global [%0], [%1], 16;"
                 :: "r"(dst), "l"(src) : "memory");
}
#define CP_COMMIT() asm volatile("cp.async.commit_group;" ::: "memory")
#define CP_WAIT2()  asm volatile("cp.async.wait_group 2;"  ::: "memory")

__device__ __forceinline__ uint32_t f2tf(float f) {
    uint32_t r;
    asm("cvt.rna.tf32.f32 %0, %1;" : "=r"(r) : "f"(f));
    return r;
}

__device__ __forceinline__ void mma_tf32(float c[4],
                                         const uint32_t a[4], const uint32_t b[2]) {
    asm volatile(
        "mma.sync.aligned.m16n8k8.row.col.f32.tf32.tf32.f32 "
        "{%0,%1,%2,%3}, {%4,%5,%6,%7}, {%8,%9}, {%0,%1,%2,%3};"
        : "+f"(c[0]), "+f"(c[1]), "+f"(c[2]), "+f"(c[3])
        : "r"(a[0]), "r"(a[1]), "r"(a[2]), "r"(a[3]), "r"(b[0]), "r"(b[1]));
}

// ---------------------------------------------------------------------------
// Pack A: fragment-major layout. Chunk index within a (mtile,kt) 32KB tile:
//   ((warp_m*4 + t)*4 + ks)*32 + lane   -> 16B quad =
//   { A[r,c], A[r+8,c], A[r,c+4], A[r+8,c+4] }  (tf32-rounded)
//   r = mtile*256 + warp_m*64 + t*16 + (lane>>2),  c = kt*32 + ks*8 + (lane&3)
// ---------------------------------------------------------------------------
__global__ void __launch_bounds__(256) pack_a_kernel(const float* __restrict__ A) {
    const uint32_t idx = blockIdx.x * 256u + threadIdx.x;     // 0 .. 4194303
    const uint32_t mtile = idx >> 18;
    const uint32_t rem   = idx & 262143u;
    const uint32_t kt    = rem >> 11;
    const uint32_t chunk = rem & 2047u;
    const uint32_t lane  = chunk & 31u;
    const uint32_t blk   = chunk >> 5;          // (warp_m*4 + t)*4 + ks
    const uint32_t ks    = blk & 3u;
    const uint32_t t     = (blk >> 2) & 3u;
    const uint32_t wm    = blk >> 4;
    const uint32_t r = mtile * 256 + wm * 64 + t * 16 + (lane >> 2);
    const uint32_t c = kt * 32 + ks * 8 + (lane & 3);
    const float* p = A + (size_t)r * KDIM + c;
    uint4 v;
    v.x = f2tf(p[0]);
    v.y = f2tf(p[(size_t)8 * KDIM]);
    v.z = f2tf(p[4]);
    v.w = f2tf(p[(size_t)8 * KDIM + 4]);
    g_Ap[idx] = v;
}

// Pack B: chunk = ((warp_n*8 + u)*4 + ks)*32 + lane -> 8B pair { B[n,c], B[n,c+4] }
//   n = ntile*128 + warp_n*64 + u*8 + (lane>>2), c = kt*32 + ks*8 + (lane&3)
// Rows n >= 1000 are zero-filled (removes all bounds logic from the GEMM).
__global__ void __launch_bounds__(256) pack_b_kernel(const float* __restrict__ B) {
    const uint32_t idx = blockIdx.x * 256u + threadIdx.x;     // 0 .. 2097151
    const uint32_t ntile = idx >> 18;
    const uint32_t rem   = idx & 262143u;
    const uint32_t kt    = rem >> 11;
    const uint32_t chunk = rem & 2047u;
    const uint32_t lane  = chunk & 31u;
    const uint32_t blk   = chunk >> 5;          // (warp_n*8 + u)*4 + ks
    const uint32_t ks    = blk & 3u;
    const uint32_t u     = (blk >> 2) & 7u;
    const uint32_t wn    = blk >> 5;
    const uint32_t n = ntile * 128 + wn * 64 + u * 8 + (lane >> 2);
    const uint32_t c = kt * 32 + ks * 8 + (lane & 3);
    uint2 v = make_uint2(0u, 0u);
    if (n < NDIM) {
        const float* p = B + (size_t)n * KDIM + c;
        v.x = f2tf(p[0]);
        v.y = f2tf(p[4]);
    }
    g_Bp[idx] = v;
}

// ---------------------------------------------------------------------------
__global__ void __launch_bounds__(THREADS, 1)
tol_gemm_tf32(float* __restrict__ C) {         // [4096, 1000]
    extern __shared__ char smem[];
    const int tid  = threadIdx.x;
    const int wid  = tid >> 5;
    const int lane = tid & 31;

    const int mtile = blockIdx.y;
    const int ntile = blockIdx.x;
    const int m0 = mtile * BM;
    const int n0 = ntile * BN;

    const int warp_m = wid >> 1;     // 0..3
    const int warp_n = wid & 1;      // 0..1

    const uint32_t sb = smem_u32(smem);

#define ISSUE_STAGE(kt_, s_) do {                                                \
        const uint32_t soff = (uint32_t)(s_) * STAGE_BYTES;                      \
        const uint4* asrc = g_Ap + ((size_t)(mtile * KTILES + (kt_))) * 2048;    \
        const uint2* bsrc = g_Bp + ((size_t)(ntile * KTILES + (kt_))) * 2048;    \
        _Pragma("unroll")                                                        \
        for (int i = 0; i < 8; i++)                                              \
            cp16(sb + soff + (uint32_t)(tid + i * 256) * 16,                     \
                 asrc + tid + i * 256);                                          \
        _Pragma("unroll")                                                        \
        for (int i = 0; i < 4; i++)                                              \
            cp16(sb + soff + A_TILE_BYTES + (uint32_t)(tid + i * 256) * 16,      \
                 bsrc + (tid + i * 256) * 2);                                    \
    } while (0)

    float acc[4][8][4];
    #pragma unroll
    for (int t = 0; t < 4; t++)
        #pragma unroll
        for (int u = 0; u < 8; u++)
            #pragma unroll
            for (int i = 0; i < 4; i++)
                acc[t][u][i] = 0.0f;

    // prologue: fill STAGES-1 = 3 stages
    #pragma unroll
    for (int p = 0; p < STAGES - 1; p++) {
        ISSUE_STAGE(p, p);
        CP_COMMIT();
    }

    // fragment double buffers
    uint32_t af[2][4][4];
    uint32_t bf[2][8][2];

#define LOAD_FRAG(buf, aS, bS, ksv) do {                                         \
        _Pragma("unroll")                                                        \
        for (int t = 0; t < 4; t++) {                                            \
            uint4 v = (aS)[((warp_m * 4 + t) * 4 + (ksv)) * 32 + lane];          \
            af[buf][t][0] = v.x; af[buf][t][1] = v.y;                            \
            af[buf][t][2] = v.z; af[buf][t][3] = v.w;                            \
        }                                                                        \
        _Pragma("unroll")                                                        \
        for (int u = 0; u < 8; u++) {                                            \
            uint2 w = (bS)[((warp_n * 8 + u) * 4 + (ksv)) * 32 + lane];          \
            bf[buf][u][0] = w.x; bf[buf][u][1] = w.y;                            \
        }                                                                        \
    } while (0)

    int s = 0;
    for (int kt = 0; kt < KTILES; kt++) {
        CP_WAIT2();
        __syncthreads();

        const uint4* aS = reinterpret_cast<const uint4*>(smem + s * STAGE_BYTES);
        const uint2* bS = reinterpret_cast<const uint2*>(smem + s * STAGE_BYTES + A_TILE_BYTES);

        // first fragment of this phase
        LOAD_FRAG(0, aS, bS, 0);

        // refill the stage consumed STAGES-1 phases ago
        const int kn = kt + STAGES - 1;
        if (kn < KTILES) {
            int sr = s + STAGES - 1; if (sr >= STAGES) sr -= STAGES;
            ISSUE_STAGE(kn, sr);
        }
        CP_COMMIT();

        // pipelined ks loop: load frag(ks+1) before mma(ks)
        #pragma unroll
        for (int ks = 0; ks < 4; ks++) {
            const int cur = ks & 1;
            if (ks < 3) LOAD_FRAG(cur ^ 1, aS, bS, ks + 1);
            #pragma unroll
            for (int t = 0; t < 4; t++)
                #pragma unroll
                for (int u = 0; u < 8; u++)
                    mma_tf32(acc[t][u], af[cur][t], bf[cur][u]);
        }

        if (++s == STAGES) s = 0;
    }

    // ---- epilogue: each warp writes its 64x64 region, guard N edge ----
    #pragma unroll
    for (int t = 0; t < 4; t++) {
        const int gr = m0 + warp_m * 64 + t * 16 + (lane >> 2);
        #pragma unroll
        for (int u = 0; u < 8; u++) {
            const int gc = n0 + warp_n * 64 + u * 8 + (lane & 3) * 2;
            if (gc < NDIM) {   // NDIM even; float2 never straddles the edge
                float2 v0 = make_float2(acc[t][u][0], acc[t][u][1]);
                float2 v1 = make_float2(acc[t][u][2], acc[t][u][3]);
                *reinterpret_cast<float2*>(C + (size_t)gr * NDIM + gc) = v0;
                *reinterpret_cast<float2*>(C + (size_t)(gr + 8) * NDIM + gc) = v1;
            }
        }
    }
}

// ---------------------------------------------------------------------------
extern "C" void kernel_launch(void* const* d_in, const int* in_sizes, int n_in,
                              void* d_out, int out_size) {
    const float* core = (const float*)d_in[0];   // [4096, 16,16,16] = [4096,4096]
    const float* wts  = (const float*)d_in[1];   // [1000, 4096]
    float* out = (float*)d_out;                  // [4096, 1000]

    // pack prepass (same stream -> ordered before GEMM; graph-capturable)
    pack_a_kernel<<<16384, 256>>>(core);
    pack_b_kernel<<<8192, 256>>>(wts);

    cudaFuncSetAttribute(tol_gemm_tf32,
                         cudaFuncAttributeMaxDynamicSharedMemorySize, SMEM_BYTES);

    dim3 grid(NDIM > 0 ? (1024 / BN) : 0, MDIM / BM, 1);   // (8, 16) = 128 CTAs
    tol_gemm_tf32<<<grid, THREADS, SMEM_BYTES>>>(out);
}

// round 7
// speedup vs baseline: 1.6104x; 1.1799x over previous
#include <cuda_runtime.h>
#include <cstdint>

// ============================================================================
// out[4096,1000] = core[4096,4096] @ weights[1000,4096]^T   (fp32)
//
// R7 vs R6 (215us): same packed fragment-major two-phase scheme, plus
//  - cross-phase fragment prefetch: ks=0 frags of phase kt+1 are loaded from
//    the next smem stage during phase kt's final ks step, removing the
//    post-barrier LDS bubble at every phase start (cp.async.wait_group 1
//    guarantees that stage is complete; it is not overwritten until the
//    phase kt+2 refill, which is behind the kt+2 barrier).
//  - kt loop unrolled by 4 so stage offsets are compile-time immediates.
// ============================================================================

#define MDIM 4096
#define NDIM 1000
#define KDIM 4096

#define BM 256
#define BN 128
#define BK 32
#define KTILES (KDIM / BK)            // 128
#define STAGES 4
#define THREADS 256

#define A_TILE_BYTES (BM * BK * 4)    // 32768
#define B_TILE_BYTES (BN * BK * 4)    // 16384
#define STAGE_BYTES  (A_TILE_BYTES + B_TILE_BYTES)   // 49152
#define SMEM_BYTES   (STAGES * STAGE_BYTES)          // 196608

// packed scratch: A' = [16 mtiles][128 kt][2048 x 16B], B' = [8 ntiles][128 kt][2048 x 8B]
__device__ uint4 g_Ap[16 * 128 * 2048];   // 64 MB
__device__ uint2 g_Bp[8 * 128 * 2048];    // 16 MB

// ---------------------------------------------------------------------------
__device__ __forceinline__ uint32_t smem_u32(const void* p) {
    uint32_t a;
    asm("{ .reg .u64 t; cvta.to.shared.u64 t, %1; cvt.u32.u64 %0, t; }" : "=r"(a) : "l"(p));
    return a;
}

__device__ __forceinline__ void cp16(uint32_t dst, const void* src) {
    asm volatile("cp.async.cg.shared.global [%0], [%1], 16;"
                 :: "r"(dst), "l"(src) : "memory");
}
#define CP_COMMIT() asm volatile("cp.async.commit_group;" ::: "memory")
#define CP_WAIT1()  asm volatile("cp.async.wait_group 1;"  ::: "memory")
#define CP_WAIT2()  asm volatile("cp.async.wait_group 2;"  ::: "memory")

__device__ __forceinline__ uint32_t f2tf(float f) {
    uint32_t r;
    asm("cvt.rna.tf32.f32 %0, %1;" : "=r"(r) : "f"(f));
    return r;
}

__device__ __forceinline__ void mma_tf32(float c[4],
                                         const uint32_t a[4], const uint32_t b[2]) {
    asm volatile(
        "mma.sync.aligned.m16n8k8.row.col.f32.tf32.tf32.f32 "
        "{%0,%1,%2,%3}, {%4,%5,%6,%7}, {%8,%9}, {%0,%1,%2,%3};"
        : "+f"(c[0]), "+f"(c[1]), "+f"(c[2]), "+f"(c[3])
        : "r"(a[0]), "r"(a[1]), "r"(a[2]), "r"(a[3]), "r"(b[0]), "r"(b[1]));
}

// ---------------------------------------------------------------------------
// Pack A: fragment-major. Chunk ((warp_m*4+t)*4+ks)*32+lane -> 16B quad
//   { A[r,c], A[r+8,c], A[r,c+4], A[r+8,c+4] }, tf32-rounded.
//   r = mtile*256 + wm*64 + t*16 + (lane>>2),  c = kt*32 + ks*8 + (lane&3)
__global__ void __launch_bounds__(256) pack_a_kernel(const float* __restrict__ A) {
    const uint32_t idx = blockIdx.x * 256u + threadIdx.x;
    const uint32_t mtile = idx >> 18;
    const uint32_t rem   = idx & 262143u;
    const uint32_t kt    = rem >> 11;
    const uint32_t chunk = rem & 2047u;
    const uint32_t lane  = chunk & 31u;
    const uint32_t blk   = chunk >> 5;
    const uint32_t ks    = blk & 3u;
    const uint32_t t     = (blk >> 2) & 3u;
    const uint32_t wm    = blk >> 4;
    const uint32_t r = mtile * 256 + wm * 64 + t * 16 + (lane >> 2);
    const uint32_t c = kt * 32 + ks * 8 + (lane & 3);
    const float* p = A + (size_t)r * KDIM + c;
    uint4 v;
    v.x = f2tf(p[0]);
    v.y = f2tf(p[(size_t)8 * KDIM]);
    v.z = f2tf(p[4]);
    v.w = f2tf(p[(size_t)8 * KDIM + 4]);
    g_Ap[idx] = v;
}

// Pack B: chunk ((warp_n*8+u)*4+ks)*32+lane -> 8B pair { B[n,c], B[n,c+4] },
// rows n >= 1000 zero-filled.
__global__ void __launch_bounds__(256) pack_b_kernel(const float* __restrict__ B) {
    const uint32_t idx = blockIdx.x * 256u + threadIdx.x;
    const uint32_t ntile = idx >> 18;
    const uint32_t rem   = idx & 262143u;
    const uint32_t kt    = rem >> 11;
    const uint32_t chunk = rem & 2047u;
    const uint32_t lane  = chunk & 31u;
    const uint32_t blk   = chunk >> 5;
    const uint32_t ks    = blk & 3u;
    const uint32_t u     = (blk >> 2) & 7u;
    const uint32_t wn    = blk >> 5;
    const uint32_t n = ntile * 128 + wn * 64 + u * 8 + (lane >> 2);
    const uint32_t c = kt * 32 + ks * 8 + (lane & 3);
    uint2 v = make_uint2(0u, 0u);
    if (n < NDIM) {
        const float* p = B + (size_t)n * KDIM + c;
        v.x = f2tf(p[0]);
        v.y = f2tf(p[4]);
    }
    g_Bp[idx] = v;
}

// ---------------------------------------------------------------------------
__global__ void __launch_bounds__(THREADS, 1)
tol_gemm_tf32(float* __restrict__ C) {         // [4096, 1000]
    extern __shared__ char smem[];
    const int tid  = threadIdx.x;
    const int wid  = tid >> 5;
    const int lane = tid & 31;

    const int mtile = blockIdx.y;
    const int ntile = blockIdx.x;
    const int m0 = mtile * BM;
    const int n0 = ntile * BN;

    const int warp_m = wid >> 1;     // 0..3
    const int warp_n = wid & 1;      // 0..1

    const uint32_t sb = smem_u32(smem);

#define ISSUE_STAGE(kt_, s_) do {                                                \
        const uint32_t soff = (uint32_t)(s_) * STAGE_BYTES;                      \
        const uint4* asrc = g_Ap + ((size_t)(mtile * KTILES + (kt_))) * 2048;    \
        const uint2* bsrc = g_Bp + ((size_t)(ntile * KTILES + (kt_))) * 2048;    \
        _Pragma("unroll")                                                        \
        for (int i = 0; i < 8; i++)                                              \
            cp16(sb + soff + (uint32_t)(tid + i * 256) * 16,                     \
                 asrc + tid + i * 256);                                          \
        _Pragma("unroll")                                                        \
        for (int i = 0; i < 4; i++)                                              \
            cp16(sb + soff + A_TILE_BYTES + (uint32_t)(tid + i * 256) * 16,      \
                 bsrc + (tid + i * 256) * 2);                                    \
    } while (0)

    float acc[4][8][4];
    #pragma unroll
    for (int t = 0; t < 4; t++)
        #pragma unroll
        for (int u = 0; u < 8; u++)
            #pragma unroll
            for (int i = 0; i < 4; i++)
                acc[t][u][i] = 0.0f;

    // prologue: fill STAGES-1 = 3 stages
    #pragma unroll
    for (int p = 0; p < STAGES - 1; p++) {
        ISSUE_STAGE(p, p);
        CP_COMMIT();
    }

    // fragment double buffers
    uint32_t af[2][4][4];
    uint32_t bf[2][8][2];

#define LOAD_FRAG(buf, aS, bS, ksv) do {                                         \
        _Pragma("unroll")                                                        \
        for (int t = 0; t < 4; t++) {                                            \
            uint4 v = (aS)[((warp_m * 4 + t) * 4 + (ksv)) * 32 + lane];          \
            af[buf][t][0] = v.x; af[buf][t][1] = v.y;                            \
            af[buf][t][2] = v.z; af[buf][t][3] = v.w;                            \
        }                                                                        \
        _Pragma("unroll")                                                        \
        for (int u = 0; u < 8; u++) {                                            \
            uint2 w = (bS)[((warp_n * 8 + u) * 4 + (ksv)) * 32 + lane];          \
            bf[buf][u][0] = w.x; bf[buf][u][1] = w.y;                            \
        }                                                                        \
    } while (0)

#define MMA_ALL(buf) do {                                                        \
        _Pragma("unroll")                                                        \
        for (int t = 0; t < 4; t++)                                              \
            _Pragma("unroll")                                                    \
            for (int u = 0; u < 8; u++)                                          \
                mma_tf32(acc[t][u], af[buf][t], bf[buf][u]);                     \
    } while (0)

#define STAGE_A(s_) reinterpret_cast<const uint4*>(smem + (s_) * STAGE_BYTES)
#define STAGE_B(s_) reinterpret_cast<const uint2*>(smem + (s_) * STAGE_BYTES + A_TILE_BYTES)

    // preload buf0 = frag(kt=0, ks=0) from stage 0
    CP_WAIT2();
    __syncthreads();
    LOAD_FRAG(0, STAGE_A(0), STAGE_B(0), 0);

    // One pipeline phase at compile-time stage S. Enters with buf0 holding
    // frag(kt, ks=0); exits with buf0 holding frag(kt+1, ks=0) read from the
    // NEXT stage (complete per wait_group 1; not overwritten until the kt+2
    // refill, which is behind the kt+2 barrier).
#define PHASE(S, kt_) do {                                                       \
        CP_WAIT1();                                                              \
        __syncthreads();                                                         \
        const int kn = (kt_) + STAGES - 1;                                       \
        if (kn < KTILES) ISSUE_STAGE(kn, ((S) + STAGES - 1) & 3);                \
        CP_COMMIT();                                                             \
        const uint4* aS = STAGE_A(S);                                            \
        const uint2* bS = STAGE_B(S);                                            \
        const uint4* aN = STAGE_A(((S) + 1) & 3);                                \
        const uint2* bN = STAGE_B(((S) + 1) & 3);                                \
        LOAD_FRAG(1, aS, bS, 1);  MMA_ALL(0);                                    \
        LOAD_FRAG(0, aS, bS, 2);  MMA_ALL(1);                                    \
        LOAD_FRAG(1, aS, bS, 3);  MMA_ALL(0);                                    \
        LOAD_FRAG(0, aN, bN, 0);  MMA_ALL(1);                                    \
    } while (0)

    for (int kt = 0; kt < KTILES; kt += 4) {
        PHASE(0, kt);
        PHASE(1, kt + 1);
        PHASE(2, kt + 2);
        PHASE(3, kt + 3);
    }

    // ---- epilogue: each warp writes its 64x64 region, guard N edge ----
    #pragma unroll
    for (int t = 0; t < 4; t++) {
        const int gr = m0 + warp_m * 64 + t * 16 + (lane >> 2);
        #pragma unroll
        for (int u = 0; u < 8; u++) {
            const int gc = n0 + warp_n * 64 + u * 8 + (lane & 3) * 2;
            if (gc < NDIM) {   // NDIM even; float2 never straddles the edge
                float2 v0 = make_float2(acc[t][u][0], acc[t][u][1]);
                float2 v1 = make_float2(acc[t][u][2], acc[t][u][3]);
                *reinterpret_cast<float2*>(C + (size_t)gr * NDIM + gc) = v0;
                *reinterpret_cast<float2*>(C + (size_t)(gr + 8) * NDIM + gc) = v1;
            }
        }
    }
}

// ---------------------------------------------------------------------------
extern "C" void kernel_launch(void* const* d_in, const int* in_sizes, int n_in,
                              void* d_out, int out_size) {
    const float* core = (const float*)d_in[0];   // [4096, 16,16,16] = [4096,4096]
    const float* wts  = (const float*)d_in[1];   // [1000, 4096]
    float* out = (float*)d_out;                  // [4096, 1000]

    // pack prepass (same stream -> ordered before GEMM; graph-capturable)
    pack_a_kernel<<<16384, 256>>>(core);
    pack_b_kernel<<<8192, 256>>>(wts);

    cudaFuncSetAttribute(tol_gemm_tf32,
                         cudaFuncAttributeMaxDynamicSharedMemorySize, SMEM_BYTES);

    dim3 grid(8, 16, 1);   // 128 CTAs = 1 clean wave
    tol_gemm_tf32<<<grid, THREADS, SMEM_BYTES>>>(out);
}